// round 15
// baseline (speedup 1.0000x reference)
#include <cuda_runtime.h>
#include <cuda_fp16.h>

// DAGProp: layered DAG, B=64 identical graphs, 11 levels x 10000 nodes,
// K=16 children per father, edges level-contiguous (dst = repeat(fathers,16)).
//   leaves:   out = tanh(x)
//   level l:  out[f] = tanh(x[f]*w_r + b_l + (w_l/16)*sum(out[children]))
// PERSISTENT kernel (all 1250 blocks co-resident at 9 blocks/SM) with a
// lightweight release/acquire grid barrier: bar.sync -> tid0 red.release,
// consumers poll ld.acquire + nanosleep. Inner loop = R11 shape: 2 fathers
// per warp, 16 LDG.64 fp16 gathers, fp32 math, HW tanh.approx. Next level's
// x + indices are preloaded across the barrier.

#define BB     64        // batch
#define NN     110000    // nodes per graph
#define NPLV   10000     // nodes per level
#define KK     16        // children per father
#define LEVELS 10        // non-leaf levels
#define NBLK   1250      // persistent grid (8 fathers/block)

// Gather-source scratch (node-major [n][b], fp16). Levels 0..LEVELS-1 used.
__device__ __half g_outH[(size_t)NPLV * LEVELS * BB];
// Grid-barrier counters, one per level; zeroed by k_pre each call.
__device__ unsigned g_ctr[LEVELS + 1];

__device__ __forceinline__ float fast_tanh(float v) {
    float r;
    asm("tanh.approx.f32 %0, %1;" : "=f"(r) : "f"(v));
    return r;
}

__device__ __forceinline__ void arrive_release(unsigned* ctr) {
    asm volatile("red.release.gpu.global.add.u32 [%0], 1;"
                 :: "l"(ctr) : "memory");
}

__device__ __forceinline__ unsigned ld_acquire(const unsigned* ctr) {
    unsigned v;
    asm volatile("ld.acquire.gpu.global.u32 %0, [%1];"
                 : "=r"(v) : "l"(ctr) : "memory");
    return v;
}

// ---------------------------------------------------------------------------
// k_pre: leaves only. Read x[:, 0:NPLV] coalesced; write tanh(x) to d_out
// (fp32, batch-major) and to g_outH (fp16, node-major via smem transpose).
// Also resets the grid-barrier counters (runs before k_main in stream order).
// ---------------------------------------------------------------------------
__global__ void k_pre(const float* __restrict__ x, float* __restrict__ out) {
    __shared__ float tile[32][33];
    const int n0 = blockIdx.x * 32;
    const int b0 = blockIdx.y * 32;
    const int tx = threadIdx.x, ty = threadIdx.y;

    if (blockIdx.x == 0 && blockIdx.y == 0 && ty == 0 && tx <= LEVELS)
        g_ctr[tx] = 0u;

    int n = n0 + tx;            // coalesced over n
    int b = b0 + ty;
    float v = 0.0f;
    if (n < NPLV) {
        v = tanhf(x[(size_t)b * NN + n]);
        out[(size_t)b * NN + n] = v;
    }
    tile[ty][tx] = v;
    __syncthreads();

    int n2 = n0 + ty;           // coalesced over b
    int b2 = b0 + tx;
    if (n2 < NPLV)
        g_outH[(size_t)n2 * BB + b2] = __float2half_rn(tile[tx][ty]);
}

// ---------------------------------------------------------------------------
// k_main: persistent. 8 fathers/block across all levels, 2 fathers/warp.
// Lane l: g = l>>4 selects father, s = l&15 owns batches 4s..4s+3 (8 B of a
// 128 B gather row). 16 LDG.64/warp cover 32 father-children. Per level:
//   wait(ctr[l-1], acquire) -> gathers -> preload next x/idx -> compute ->
//   write g_outH -> bar -> tid0 red.release(ctr[l]) -> write d_out.
// ---------------------------------------------------------------------------
__global__ void __launch_bounds__(128, 9) k_main(
    const int* __restrict__ srcidx,   // edge_index row 0 (children)
    const float* __restrict__ x,
    const float* __restrict__ wl,
    const float* __restrict__ bl,
    const float* __restrict__ wr,
    float* __restrict__ out)
{
    __shared__ float sm_x[8][68];   // row stride 68 floats (16B-aligned rows)
    __shared__ float sm_o[8][68];

    const int tid = threadIdx.x;
    const int w   = tid >> 5;             // warp 0..3
    const int l   = tid & 31;
    const int g   = l >> 4;               // father select within warp
    const int s   = l & 15;               // 4-batch group
    const int flb = blockIdx.x * 8;       // first father (local) of this block
    const int flw = flb + 2 * w;          // warp's first father
    const int fl  = flw + g;              // this lane's father (local)
    const int fo  = tid & 7;
    const int br  = tid >> 3;             // 0..15

    const float Wr = __ldg(wr);
    const float Bl = __ldg(bl);
    const float scale = __ldg(wl) * (1.0f / (float)KK);

    // --- Preload level 1's indices + x ---
    int idx_c = __ldg(srcidx + (size_t)flw * KK + l);
    size_t col = (size_t)(NPLV + flb + fo);
    float x0 = x[(size_t)br        * NN + col];
    float x1 = x[(size_t)(br + 16) * NN + col];
    float x2 = x[(size_t)(br + 32) * NN + col];
    float x3 = x[(size_t)(br + 48) * NN + col];

    for (int level = 1; level <= LEVELS; level++) {
        // --- Grid barrier: level-(l-1) g_outH writes visible (acquire) ---
        if (level > 1) {
            if (tid == 0) {
                while (ld_acquire(&g_ctr[level - 1]) < (unsigned)NBLK)
                    __nanosleep(64);
            }
        }
        __syncthreads();

        // --- 16 LDG.64 gathers: half-warp g reads child rows of flw+g ---
        const __half* ob = g_outH + 4 * s;
        uint2 v[16];
        #pragma unroll
        for (int j = 0; j < 16; j++) {
            const int c = __shfl_sync(0xffffffffu, idx_c, j, 16);
            v[j] = *reinterpret_cast<const uint2*>(ob + (size_t)c * BB);
        }

        // --- Preload NEXT level's indices + x (complete during compute) ---
        int idx_n = 0;
        size_t ncol = 0;
        float n0 = 0.f, n1 = 0.f, n2 = 0.f, n3 = 0.f;
        if (level < LEVELS) {
            idx_n = __ldg(srcidx + ((size_t)level * NPLV + flw) * KK + l);
            ncol = (size_t)((level + 1) * NPLV + flb + fo);
            n0 = x[(size_t)br        * NN + ncol];
            n1 = x[(size_t)(br + 16) * NN + ncol];
            n2 = x[(size_t)(br + 32) * NN + ncol];
            n3 = x[(size_t)(br + 48) * NN + ncol];
        }

        // --- x transpose through smem ---
        sm_x[fo][br]      = x0;
        sm_x[fo][br + 16] = x1;
        sm_x[fo][br + 32] = x2;
        sm_x[fo][br + 48] = x3;
        __syncthreads();
        const float4 xv = *reinterpret_cast<const float4*>(&sm_x[2 * w + g][4 * s]);

        // --- Convert + reduce in fp32 (4 independent chains) ---
        float s0 = 0.f, s1 = 0.f, s2 = 0.f, s3 = 0.f;
        #pragma unroll
        for (int j = 0; j < 16; j++) {
            const __half2 hlo = *reinterpret_cast<const __half2*>(&v[j].x);
            const __half2 hhi = *reinterpret_cast<const __half2*>(&v[j].y);
            const float2 flo = __half22float2(hlo);
            const float2 fhi = __half22float2(hhi);
            s0 += flo.x; s1 += flo.y; s2 += fhi.x; s3 += fhi.y;
        }

        float4 o;
        o.x = fast_tanh(fmaf(s0, scale, fmaf(xv.x, Wr, Bl)));
        o.y = fast_tanh(fmaf(s1, scale, fmaf(xv.y, Wr, Bl)));
        o.z = fast_tanh(fmaf(s2, scale, fmaf(xv.z, Wr, Bl)));
        o.w = fast_tanh(fmaf(s3, scale, fmaf(xv.w, Wr, Bl)));

        if (level < LEVELS) {   // last level is never a gather source
            uint2 oh;
            *reinterpret_cast<__half2*>(&oh.x) = __floats2half2_rn(o.x, o.y);
            *reinterpret_cast<__half2*>(&oh.y) = __floats2half2_rn(o.z, o.w);
            *reinterpret_cast<uint2*>(
                g_outH + (size_t)(level * NPLV + fl) * BB + 4 * s) = oh;
        }

        // --- Stage output; release-arrive (bar gives CTA-wide HB into tid0) ---
        *reinterpret_cast<float4*>(&sm_o[2 * w + g][4 * s]) = o;
        __syncthreads();
        if (level < LEVELS && tid == 0)
            arrive_release(&g_ctr[level]);

        // --- Final output [B, N] (after arrive: off the critical path) ---
        out[(size_t)br        * NN + col] = sm_o[fo][br];
        out[(size_t)(br + 16) * NN + col] = sm_o[fo][br + 16];
        out[(size_t)(br + 32) * NN + col] = sm_o[fo][br + 32];
        out[(size_t)(br + 48) * NN + col] = sm_o[fo][br + 48];

        // --- Rotate pipeline registers ---
        idx_c = idx_n;
        col = ncol;
        x0 = n0; x1 = n1; x2 = n2; x3 = n3;
    }
}

// ---------------------------------------------------------------------------
// Launch (graph-capturable, allocation-free).
// Inputs: x, w_l, b_l, w_r, edge_index, num_levels
// ---------------------------------------------------------------------------
extern "C" void kernel_launch(void* const* d_in, const int* in_sizes, int n_in,
                              void* d_out, int out_size) {
    const float* x  = (const float*)d_in[0];
    const float* wl = (const float*)d_in[1];
    const float* bl = (const float*)d_in[2];
    const float* wr = (const float*)d_in[3];
    const int*   ei = (const int*)d_in[4];   // [2, E]; row 0 = children
    float* out = (float*)d_out;

    dim3 blk(32, 32);
    dim3 grd((NPLV + 31) / 32, BB / 32);
    k_pre<<<grd, blk>>>(x, out);

    k_main<<<NBLK, 128>>>(ei, x, wl, bl, wr, out);
}

// round 17
// speedup vs baseline: 1.9267x; 1.9267x over previous
#include <cuda_runtime.h>
#include <cuda_fp16.h>

// DAGProp: layered DAG, B=64 identical graphs, 11 levels x 10000 nodes,
// K=16 children per father, edges level-contiguous (dst = repeat(fathers,16)).
//   leaves:   out = tanh(x)
//   level l:  out[f] = tanh(x[f]*w_r + b_l + (w_l/16)*sum(out[children]))
// One kernel per level (persistent variants measured 2x slower; reverted).
// FP16 node-major gather scratch (128 B/row), fp32 math, HW tanh.approx.
// k_level: 2 fathers/warp, 16 LDG.64 gathers, direct per-lane x loads
// (no input smem staging), vectorized STG.128 output drain. 1250 blocks
// = single wave at 9 blocks/SM.

#define BB     64        // batch
#define NN     110000    // nodes per graph
#define NPLV   10000     // nodes per level
#define KK     16        // children per father
#define LEVELS 10        // non-leaf levels

// Gather-source scratch (node-major [n][b], fp16). Levels 0..LEVELS-1 used.
__device__ __half g_outH[(size_t)NPLV * LEVELS * BB];

__device__ __forceinline__ float fast_tanh(float v) {
    float r;
    asm("tanh.approx.f32 %0, %1;" : "=f"(r) : "f"(v));
    return r;
}

// ---------------------------------------------------------------------------
// k_pre: leaves only. Read x[:, 0:NPLV] coalesced; write tanh(x) to d_out
// (fp32, batch-major) and to g_outH (fp16, node-major via smem transpose).
// ---------------------------------------------------------------------------
__global__ void k_pre(const float* __restrict__ x, float* __restrict__ out) {
    __shared__ float tile[32][33];
    const int n0 = blockIdx.x * 32;
    const int b0 = blockIdx.y * 32;
    const int tx = threadIdx.x, ty = threadIdx.y;

    int n = n0 + tx;            // coalesced over n
    int b = b0 + ty;
    float v = 0.0f;
    if (n < NPLV) {
        v = tanhf(x[(size_t)b * NN + n]);
        out[(size_t)b * NN + n] = v;
    }
    tile[ty][tx] = v;
    __syncthreads();

    int n2 = n0 + ty;           // coalesced over b
    int b2 = b0 + tx;
    if (n2 < NPLV)
        g_outH[(size_t)n2 * BB + b2] = __float2half_rn(tile[tx][ty]);
}

// ---------------------------------------------------------------------------
// k_level: 8 fathers / 128-thread block, 2 fathers / warp.
// Lane l: g = l>>4 selects father (2w+g), s = l&15; lane owns batches
// 4s..4s+3 (8 B of a 128 B gather row). 16 LDG.64 per warp cover all 32
// father-child gathers; indices via one coalesced load + shfl(width=16).
// x is loaded directly per lane (4 scalar LDG; block covers full 32 B
// sectors, L1 shares across warps). Output drained as STG.128 per thread.
// ---------------------------------------------------------------------------
__global__ void __launch_bounds__(128, 9) k_level(
    const int* __restrict__ srcidx,   // edge_index row 0 (children)
    const float* __restrict__ x,
    const float* __restrict__ wl,
    const float* __restrict__ bl,
    const float* __restrict__ wr,
    float* __restrict__ out,
    int level)
{
    __shared__ float sm_o[8][68];   // row stride 68 floats (16B-aligned rows)

    const int tid = threadIdx.x;
    const int w   = tid >> 5;             // warp 0..3
    const int l   = tid & 31;
    const int g   = l >> 4;               // father select within warp
    const int s   = l & 15;               // 4-batch group
    const int flb = blockIdx.x * 8;       // first father (local) of this block
    const int flw = flb + 2 * w;          // warp's first father
    const int fl  = flw + g;              // this lane's father (local)
    const size_t f = (size_t)(level * NPLV + fl);

    // --- Child indices: 32 consecutive ints = both fathers of this warp ---
    const int myidx = __ldg(srcidx + ((size_t)(level - 1) * NPLV + flw) * KK + l);

    // --- Direct x loads for this lane's 4 batches (L1-shared sectors) ---
    const float xv0 = __ldg(x + (size_t)(4 * s + 0) * NN + f);
    const float xv1 = __ldg(x + (size_t)(4 * s + 1) * NN + f);
    const float xv2 = __ldg(x + (size_t)(4 * s + 2) * NN + f);
    const float xv3 = __ldg(x + (size_t)(4 * s + 3) * NN + f);

    // --- 16 LDG.64 gathers: half-warp g reads child rows of father flw+g ---
    const __half* ob = g_outH + 4 * s;
    uint2 v[16];
    #pragma unroll
    for (int j = 0; j < 16; j++) {
        const int c = __shfl_sync(0xffffffffu, myidx, j, 16);
        v[j] = *reinterpret_cast<const uint2*>(ob + (size_t)c * BB);
    }

    const float Wr = __ldg(wr);
    const float Bl = __ldg(bl);
    const float scale = __ldg(wl) * (1.0f / (float)KK);

    // --- Convert + reduce in fp32 (4 independent chains) ---
    float s0 = 0.f, s1 = 0.f, s2 = 0.f, s3 = 0.f;
    #pragma unroll
    for (int j = 0; j < 16; j++) {
        const __half2 hlo = *reinterpret_cast<const __half2*>(&v[j].x);
        const __half2 hhi = *reinterpret_cast<const __half2*>(&v[j].y);
        const float2 flo = __half22float2(hlo);
        const float2 fhi = __half22float2(hhi);
        s0 += flo.x; s1 += flo.y; s2 += fhi.x; s3 += fhi.y;
    }

    float4 o;
    o.x = fast_tanh(fmaf(s0, scale, fmaf(xv0, Wr, Bl)));
    o.y = fast_tanh(fmaf(s1, scale, fmaf(xv1, Wr, Bl)));
    o.z = fast_tanh(fmaf(s2, scale, fmaf(xv2, Wr, Bl)));
    o.w = fast_tanh(fmaf(s3, scale, fmaf(xv3, Wr, Bl)));

    if (level < LEVELS) {   // last level is never a gather source
        uint2 oh;
        *reinterpret_cast<__half2*>(&oh.x) = __floats2half2_rn(o.x, o.y);
        *reinterpret_cast<__half2*>(&oh.y) = __floats2half2_rn(o.z, o.w);
        *reinterpret_cast<uint2*>(g_outH + f * BB + 4 * s) = oh;
    }

    // --- Final output [B, N]: stage in smem, drain as STG.128 ---
    *reinterpret_cast<float4*>(&sm_o[2 * w + g][4 * s]) = o;
    __syncthreads();

    const int row   = tid >> 1;           // batch 0..63
    const int chunk = tid & 1;            // 4-col chunk within block's 8 cols
    float4 ov;
    ov.x = sm_o[4 * chunk + 0][row];
    ov.y = sm_o[4 * chunk + 1][row];
    ov.z = sm_o[4 * chunk + 2][row];
    ov.w = sm_o[4 * chunk + 3][row];
    *reinterpret_cast<float4*>(
        out + (size_t)row * NN + (size_t)(level * NPLV + flb + 4 * chunk)) = ov;
}

// ---------------------------------------------------------------------------
// Launch (graph-capturable, allocation-free).
// Inputs: x, w_l, b_l, w_r, edge_index, num_levels
// ---------------------------------------------------------------------------
extern "C" void kernel_launch(void* const* d_in, const int* in_sizes, int n_in,
                              void* d_out, int out_size) {
    const float* x  = (const float*)d_in[0];
    const float* wl = (const float*)d_in[1];
    const float* bl = (const float*)d_in[2];
    const float* wr = (const float*)d_in[3];
    const int*   ei = (const int*)d_in[4];   // [2, E]; row 0 = children
    float* out = (float*)d_out;

    dim3 blk(32, 32);
    dim3 grd((NPLV + 31) / 32, BB / 32);
    k_pre<<<grd, blk>>>(x, out);

    const int blocks = NPLV / 8;   // 1250 — single wave
    for (int l = 1; l <= LEVELS; l++) {
        k_level<<<blocks, 128>>>(ei, x, wl, bl, wr, out, l);
    }
}